// round 11
// baseline (speedup 1.0000x reference)
#include <cuda_runtime.h>
#include <cuda_bf16.h>
#include <cstdint>
#include <math.h>

#define HH 192
#define WWID 192
#define HW (192*192)
#define NB 4
#define ND 8
#define NCTA (6 * 24 * NB)      // conv grid CTAs = 576

// ======================= mma / ldmatrix helpers (sm_80+ PTX) ================
__device__ __forceinline__ void ldmx4(uint32_t addr, uint32_t* r) {
    asm volatile("ldmatrix.sync.aligned.m8n8.x4.shared.b16 {%0,%1,%2,%3}, [%4];"
        : "=r"(r[0]), "=r"(r[1]), "=r"(r[2]), "=r"(r[3]) : "r"(addr));
}
__device__ __forceinline__ void ldmx2(uint32_t addr, uint32_t* r) {
    asm volatile("ldmatrix.sync.aligned.m8n8.x2.shared.b16 {%0,%1}, [%2];"
        : "=r"(r[0]), "=r"(r[1]) : "r"(addr));
}
__device__ __forceinline__ void mma16816(float* d, const uint32_t* a, uint2 b) {
    asm volatile("mma.sync.aligned.m16n8k16.row.col.f32.bf16.bf16.f32 "
        "{%0,%1,%2,%3}, {%4,%5,%6,%7}, {%8,%9}, {%0,%1,%2,%3};"
        : "+f"(d[0]), "+f"(d[1]), "+f"(d[2]), "+f"(d[3])
        : "r"(a[0]), "r"(a[1]), "r"(a[2]), "r"(a[3]), "r"(b.x), "r"(b.y));
}
__device__ __forceinline__ void mma1688(float* d, const uint32_t* a, uint32_t b) {
    asm volatile("mma.sync.aligned.m16n8k8.row.col.f32.bf16.bf16.f32 "
        "{%0,%1,%2,%3}, {%4,%5}, {%6}, {%0,%1,%2,%3};"
        : "+f"(d[0]), "+f"(d[1]), "+f"(d[2]), "+f"(d[3])
        : "r"(a[0]), "r"(a[1]), "r"(b));
}
__device__ __forceinline__ uint32_t smem_u32(const void* p) {
    uint32_t a;
    asm("{ .reg .u64 t; cvta.to.shared.u64 t, %1; cvt.u32.u64 %0, t; }" : "=r"(a) : "l"(p));
    return a;
}
__device__ __forceinline__ unsigned short bfbits(float v) {
    return __bfloat16_as_ushort(__float2bfloat16(v));
}
__device__ __forceinline__ float fsig(float x) {
    return __fdividef(1.f, 1.f + __expf(-x));
}
__device__ __forceinline__ float ftanh(float x) {
    return 1.f - __fdividef(2.f, __expf(2.f * x) + 1.f);
}

// ======================= scratch ============================================
__device__ float g_hs[NB * 8 * HW];
__device__ float g_r [NB * 40 * HW];     // [c_state(8) | q(32)]
__device__ float g_y0[NB * 40 * HW];
__device__ float g_y1[NB * 40 * HW];
__device__ float g_pp0[NCTA * 80];       // per-CTA partial (sum|sumsq) for y0
__device__ float g_pp1[NCTA * 80];       // ... for y1
__device__ float g_st0[80];              // scale|shift for y0
__device__ float g_st1[80];              // scale|shift for y1
__device__ float g_Wg[56 * 40 * 9];
__device__ float g_bg[56];
__device__ float g_Who[16 * 40 * 25];    // fused h(3x3 embedded) + out(5x5)
__device__ float g_bho[16];
// packed mma weight fragments (k16 pairs + k8 tail), bf16 hi/lo terms
__device__ uint2    g_w0k16[25 * 2 * 5 * 2 * 32];
__device__ uint32_t g_w0k8 [25 * 5 * 2 * 32];
__device__ uint2    g_w1k16[25 * 2 * 5 * 2 * 32];
__device__ uint32_t g_w1k8 [25 * 5 * 2 * 32];
__device__ uint2    g_wgk16[9 * 2 * 7 * 2 * 32];
__device__ uint32_t g_wgk8 [9 * 7 * 2 * 32];
__device__ uint2    g_whk16[25 * 2 * 2 * 2 * 32];
__device__ uint32_t g_whk8 [25 * 2 * 2 * 32];

// ======================= setup kernel 1: zero state + build Wg/Who ==========
__global__ void init0(const float* __restrict__ Wf, const float* __restrict__ bf,
                      const float* __restrict__ Wi, const float* __restrict__ bi,
                      const float* __restrict__ Wc, const float* __restrict__ bc,
                      const float* __restrict__ Wq, const float* __restrict__ bq,
                      const float* __restrict__ Wh, const float* __restrict__ bh,
                      const float* __restrict__ W2, const float* __restrict__ b2w) {
    int stride = gridDim.x * blockDim.x;
    int i0 = blockIdx.x * blockDim.x + threadIdx.x;
    for (int i = i0; i < NB * 8 * HW; i += stride) g_hs[i] = 0.f;
    for (int i = i0; i < NB * 40 * HW; i += stride) g_r[i] = 0.f;

    const int WSZ = 40 * 9;
    int i = i0;
    if (i < 56 * WSZ) {
        int cout = i / WSZ, rest = i - cout * WSZ;
        float v;
        if (cout < 8)       v = Wf[cout * WSZ + rest];
        else if (cout < 16) v = Wi[(cout - 8) * WSZ + rest];
        else if (cout < 24) v = Wc[(cout - 16) * WSZ + rest];
        else                v = Wq[(cout - 24) * WSZ + rest];
        g_Wg[i] = v;
    }
    if (i < 56) {
        float v;
        if (i < 8)       v = bf[i];
        else if (i < 16) v = bi[i - 8];
        else if (i < 24) v = bc[i - 16];
        else             v = bq[i - 24];
        g_bg[i] = v;
    }
    if (i < 16 * 40 * 25) {
        int tap = i % 25; int rest = i / 25;
        int k = rest % 40; int nn = rest / 40;
        int ky = tap / 5, kx = tap % 5;
        float v = 0.f;
        if (nn < 8) {
            if (ky >= 1 && ky <= 3 && kx >= 1 && kx <= 3)
                v = Wh[(nn * 40 + k) * 9 + (ky - 1) * 3 + (kx - 1)];
        } else if (nn < 11) {
            v = W2[((nn - 8) * 40 + k) * 25 + tap];
        }
        g_Who[i] = v;
    }
    if (i < 16) g_bho[i] = (i < 8) ? bh[i] : (i < 11 ? b2w[i - 8] : 0.f);
}

// ======================= setup kernel 2: pack all mma fragments =============
__device__ void pk16_one(const float* __restrict__ W, uint2* __restrict__ dst,
                         int TAPS, int NT, int i) {
    int lane = i & 31; int r = i >> 5;
    int term = r & 1; r >>= 1;
    int nt = r % NT;  r /= NT;
    int kt = r & 1;   int tap = r >> 1;
    int nn = nt * 8 + (lane >> 2);
    int k0 = kt * 16 + (lane & 3) * 2;
    unsigned short h[4];
#pragma unroll
    for (int j = 0; j < 4; j++) {
        int kk = k0 + (j & 1) + (j >> 1) * 8;
        float v = W[(nn * 40 + kk) * TAPS + tap];
        unsigned short hb = bfbits(v);
        if (term == 0) h[j] = hb;
        else h[j] = bfbits(v - __bfloat162float(__ushort_as_bfloat16(hb)));
    }
    dst[i] = make_uint2((uint32_t)h[0] | ((uint32_t)h[1] << 16),
                        (uint32_t)h[2] | ((uint32_t)h[3] << 16));
}
__device__ void pk8_one(const float* __restrict__ W, uint32_t* __restrict__ dst,
                        int TAPS, int NT, int i) {
    int lane = i & 31; int r = i >> 5;
    int term = r & 1; r >>= 1;
    int nt = r % NT;  int tap = r / NT;
    int nn = nt * 8 + (lane >> 2);
    int k0 = 32 + (lane & 3) * 2;
    unsigned short h[2];
#pragma unroll
    for (int j = 0; j < 2; j++) {
        float v = W[(nn * 40 + k0 + j) * TAPS + tap];
        unsigned short hb = bfbits(v);
        if (term == 0) h[j] = hb;
        else h[j] = bfbits(v - __bfloat162float(__ushort_as_bfloat16(hb)));
    }
    dst[i] = (uint32_t)h[0] | ((uint32_t)h[1] << 16);
}

// segment sizes (exact fragment counts):
//   w0k16: 25*2*5*2*32 = 16000   -> [0, 16000)
//   w0k8 : 25*5*2*32   =  8000   -> [16000, 24000)
//   w1k16: 16000                 -> [24000, 40000)
//   w1k8 :  8000                 -> [40000, 48000)
//   wgk16: 9*2*7*2*32  =  8064   -> [48000, 56064)
//   wgk8 : 9*7*2*32    =  4032   -> [56064, 60096)
//   whk16: 25*2*2*2*32 =  6400   -> [60096, 66496)
//   whk8 : 25*2*2*32   =  3200   -> [66496, 69696)
#define FRAG_TOTAL 69696
__global__ void prep_frags(const float* __restrict__ W0, const float* __restrict__ W1) {
    int i = blockIdx.x * blockDim.x + threadIdx.x;
    if      (i < 16000) pk16_one(W0, g_w0k16, 25, 5, i);
    else if (i < 24000) pk8_one (W0, g_w0k8,  25, 5, i - 16000);
    else if (i < 40000) pk16_one(W1, g_w1k16, 25, 5, i - 24000);
    else if (i < 48000) pk8_one (W1, g_w1k8,  25, 5, i - 40000);
    else if (i < 56064) pk16_one(g_Wg, g_wgk16, 9, 7, i - 48000);
    else if (i < 60096) pk8_one (g_Wg, g_wgk8,  9, 7, i - 56064);
    else if (i < 66496) pk16_one(g_Who, g_whk16, 25, 2, i - 60096);
    else if (i < 69696) pk8_one (g_Who, g_whk8,  25, 2, i - 66496);
}

// ======================= BN partial reduce: [576][80] -> scale/shift[80] ====
__global__ void bn_reduce(const float* __restrict__ pp, const float* __restrict__ gamma,
                          const float* __restrict__ beta, float* __restrict__ st) {
    __shared__ float red[240];
    int tid = threadIdx.x;
    if (tid < 240) {
        int c = tid % 80, p = tid / 80;
        float a = 0.f;
        const float* q = pp + (size_t)p * 192 * 80 + c;
#pragma unroll 8
        for (int j = 0; j < 192; j++) a += q[j * 80];
        red[tid] = a;
    }
    __syncthreads();
    if (tid < 40) {
        float S = red[tid] + red[80 + tid] + red[160 + tid];
        float Q = red[40 + tid] + red[120 + tid] + red[200 + tid];
        const float Ninv = 1.f / (float)(NB * HW);
        float mean = S * Ninv;
        float var  = Q * Ninv - mean * mean;
        float sc   = gamma[tid] * rsqrtf(var + 1e-5f);
        st[tid] = sc;
        st[40 + tid] = beta[tid] - mean * sc;
    }
}

// ======================= generic mma conv (CIN=40, bf16 3-term, K=40) =======
// CTA: 256 thr / 8 warps; out tile 32x8 pixels; COUT = NT*8.
// MODE 0: plain 40-ch output (STATS: also emit per-CTA BN partials).
// MODE 1: LSTM epilogue -> out = r buffer (old c in ch0-7), bias = gate biases.
// MODE 2: HOUT epilogue -> out = h-state (8ch) + out2 = p_depth (3ch), biased.
// PREOP: stats_in = precomputed [scale(40)|shift(40)].
#define ASTRIDE 56
#define NTHR 256

template<int KK, int NT, int CA, bool PREOP, int MODE, bool STATS>
__global__ void __launch_bounds__(NTHR, 2)
conv_mma(const float* __restrict__ inA, int strideA,
         const float* __restrict__ inB, int strideB,
         const uint2* __restrict__ wk16,
         const uint32_t* __restrict__ wk8,
         const float* __restrict__ bias,
         const float* __restrict__ stats_in,
         float* __restrict__ ppout,
         float* __restrict__ out,
         float* __restrict__ out2)
{
    constexpr int TW = 32 + KK - 1;
    constexpr int TH = 8 + KK - 1;
    constexpr int NPIX = TW * TH;
    constexpr int PADK = KK / 2;
    constexpr int APL = NPIX * ASTRIDE * 2;     // bytes per bf16 plane

    extern __shared__ char dsm[];
    __shared__ float s_sc[40], s_sh[40];
    __shared__ float s_bias[56];
    __shared__ float s_part[STATS ? 8 * 80 : 1];
    __nv_bfloat16* Ah = (__nv_bfloat16*)dsm;
    __nv_bfloat16* Al = (__nv_bfloat16*)(dsm + APL);

    const int tid = threadIdx.x;
    const int w = tid >> 5, lane = tid & 31;
    const int bx = blockIdx.x, by = blockIdx.y, n = blockIdx.z;

    if constexpr (MODE == 1) {
        if (tid < 56) s_bias[tid] = bias[tid];
    }
    if constexpr (MODE == 2) {
        if (tid < 16) s_bias[tid] = bias[tid];
    }
    if constexpr (PREOP) {
        if (tid < 40) { s_sc[tid] = stats_in[tid]; s_sh[tid] = stats_in[40 + tid]; }
        __syncthreads();
    }

    // ---- stage input tile (fused concat), split bf16 hi/lo -----------------
    const int x0 = bx * 32 - PADK, y0 = by * 8 - PADK;
    for (int i = tid; i < 40 * NPIX; i += NTHR) {
        int cin = i / NPIX, pix = i - cin * NPIX;
        int pr = pix / TW, pc = pix - pr * TW;
        int yy = y0 + pr, xx = x0 + pc;
        float v = 0.f;
        if (yy >= 0 && yy < HH && xx >= 0 && xx < WWID) {
            const float* src = (cin < CA)
                ? (inA + (size_t)n * strideA + (size_t)cin * HW)
                : (inB + (size_t)n * strideB + (size_t)(cin - CA) * HW);
            v = src[yy * WWID + xx];
            if constexpr (PREOP) v = fmaxf(fmaf(s_sc[cin], v, s_sh[cin]), 0.f);
        }
        __nv_bfloat16 h = __float2bfloat16(v);
        __nv_bfloat16 l = __float2bfloat16(v - __bfloat162float(h));
        Ah[pix * ASTRIDE + cin] = h;
        Al[pix * ASTRIDE + cin] = l;
    }
    __syncthreads();

    const uint32_t ah_base = smem_u32(Ah);
    const uint32_t al_base = ah_base + APL;
    const int lrow = lane & 15;
    const int lcolB = (lane >> 4) * 16;

    float d[2][NT][4];
#pragma unroll
    for (int mt = 0; mt < 2; mt++)
#pragma unroll
        for (int nt = 0; nt < NT; nt++)
#pragma unroll
            for (int j = 0; j < 4; j++) d[mt][nt][j] = 0.f;

    for (int tap = 0; tap < KK * KK; tap++) {
        int ky = tap / KK, kx = tap - ky * KK;
        int rowbase = (w + ky) * TW + kx;

        uint32_t a_h[2][2][4], a_l[2][2][4];   // [kt][mt]
        uint32_t a_h8[2][2], a_l8[2][2];       // [mt]
#pragma unroll
        for (int mt = 0; mt < 2; mt++) {
            uint32_t rb = (uint32_t)(rowbase + mt * 16 + lrow) * (ASTRIDE * 2);
            ldmx4(ah_base + rb + lcolB, a_h[0][mt]);
            ldmx4(ah_base + rb + 32 + lcolB, a_h[1][mt]);
            ldmx2(ah_base + rb + 64, a_h8[mt]);
            ldmx4(al_base + rb + lcolB, a_l[0][mt]);
            ldmx4(al_base + rb + 32 + lcolB, a_l[1][mt]);
            ldmx2(al_base + rb + 64, a_l8[mt]);
        }

        const uint2* wt16 = wk16 + tap * (2 * NT * 2 * 32);
        const uint32_t* wt8 = wk8 + tap * (NT * 2 * 32);
#pragma unroll
        for (int kt = 0; kt < 2; kt++) {
#pragma unroll
            for (int nt = 0; nt < NT; nt++) {
                uint2 bh = wt16[((kt * NT + nt) * 2 + 0) * 32 + lane];
                uint2 bl = wt16[((kt * NT + nt) * 2 + 1) * 32 + lane];
#pragma unroll
                for (int mt = 0; mt < 2; mt++) {
                    mma16816(d[mt][nt], a_h[kt][mt], bh);
                    mma16816(d[mt][nt], a_l[kt][mt], bh);
                    mma16816(d[mt][nt], a_h[kt][mt], bl);
                }
            }
        }
#pragma unroll
        for (int nt = 0; nt < NT; nt++) {
            uint32_t bh8 = wt8[(nt * 2 + 0) * 32 + lane];
            uint32_t bl8 = wt8[(nt * 2 + 1) * 32 + lane];
#pragma unroll
            for (int mt = 0; mt < 2; mt++) {
                mma1688(d[mt][nt], a_h8[mt], bh8);
                mma1688(d[mt][nt], a_l8[mt], bh8);
                mma1688(d[mt][nt], a_h8[mt], bl8);
            }
        }
    }

    if constexpr (MODE == 1) {
        // ---- stash D (256 pix x 56 ch) to smem, then LSTM pointwise --------
        __syncthreads();                      // A planes dead; reuse dsm
        float* sd = (float*)dsm;              // [256][57]
#pragma unroll
        for (int mt = 0; mt < 2; mt++) {
            int px = mt * 16 + (lane >> 2);
#pragma unroll
            for (int nt = 0; nt < NT; nt++) {
                int c = nt * 8 + (lane & 3) * 2;
                sd[(w * 32 + px) * 57 + c]           = d[mt][nt][0];
                sd[(w * 32 + px) * 57 + c + 1]       = d[mt][nt][1];
                sd[(w * 32 + px + 8) * 57 + c]       = d[mt][nt][2];
                sd[(w * 32 + px + 8) * 57 + c + 1]   = d[mt][nt][3];
            }
        }
        __syncthreads();
        const float* sp = sd + tid * 57;
        int gy = by * 8 + (tid >> 5);
        int gx = bx * 32 + (tid & 31);
        float* rb = out + (size_t)n * 40 * HW + gy * WWID + gx;
#pragma unroll
        for (int c = 0; c < 8; c++) {
            float f  = fsig(sp[c] + s_bias[c]);
            float ii = fsig(sp[8 + c] + s_bias[8 + c]);
            float gg = ftanh(sp[16 + c] + s_bias[16 + c]);
            float co = rb[(size_t)c * HW];
            rb[(size_t)c * HW] = f * co + ii * gg;
        }
#pragma unroll
        for (int j = 0; j < 32; j++) {
            rb[(size_t)(8 + j) * HW] = fsig(sp[24 + j] + s_bias[24 + j]);
        }
    } else if constexpr (MODE == 2) {
        // ---- dual epilogue: nt0 -> h-state (8ch), nt1 -> p_depth (3ch) -----
        const int gy = by * 8 + w;
#pragma unroll
        for (int mt = 0; mt < 2; mt++) {
            int gx = bx * 32 + mt * 16 + (lane >> 2);
            {
                int c = (lane & 3) * 2;
                float* hb = out + ((size_t)n * 8 + c) * HW + gy * WWID + gx;
                hb[0]      = d[mt][0][0] + s_bias[c];
                hb[HW]     = d[mt][0][1] + s_bias[c + 1];
                hb[8]      = d[mt][0][2] + s_bias[c];
                hb[HW + 8] = d[mt][0][3] + s_bias[c + 1];
            }
            {
                int oc = (lane & 3) * 2;
                if (oc < 3) {
                    float* ob = out2 + (size_t)n * 3 * ND * HW
                              + (size_t)oc * ND * HW + gy * WWID + gx;
                    ob[0] = d[mt][1][0] + s_bias[8 + oc];
                    ob[8] = d[mt][1][2] + s_bias[8 + oc];
                    if (oc + 1 < 3) {
                        ob[(size_t)ND * HW]     = d[mt][1][1] + s_bias[9 + oc];
                        ob[(size_t)ND * HW + 8] = d[mt][1][3] + s_bias[9 + oc];
                    }
                }
            }
        }
    } else {
        const int gy = by * 8 + w;
#pragma unroll
        for (int mt = 0; mt < 2; mt++) {
            int gx = bx * 32 + mt * 16 + (lane >> 2);
#pragma unroll
            for (int nt = 0; nt < NT; nt++) {
                int c = nt * 8 + (lane & 3) * 2;
                float* ob = out + ((size_t)n * 40 + c) * HW + gy * WWID + gx;
                ob[0]      = d[mt][nt][0];
                ob[HW]     = d[mt][nt][1];
                ob[8]      = d[mt][nt][2];
                ob[HW + 8] = d[mt][nt][3];
            }
        }
        if constexpr (STATS) {
            // per-CTA BN partials: sum/sumsq per channel over 256 pixels
#pragma unroll
            for (int nt = 0; nt < NT; nt++) {
                float s0 = d[0][nt][0] + d[0][nt][2] + d[1][nt][0] + d[1][nt][2];
                float s1 = d[0][nt][1] + d[0][nt][3] + d[1][nt][1] + d[1][nt][3];
                float q0 = d[0][nt][0]*d[0][nt][0] + d[0][nt][2]*d[0][nt][2]
                         + d[1][nt][0]*d[1][nt][0] + d[1][nt][2]*d[1][nt][2];
                float q1 = d[0][nt][1]*d[0][nt][1] + d[0][nt][3]*d[0][nt][3]
                         + d[1][nt][1]*d[1][nt][1] + d[1][nt][3]*d[1][nt][3];
#pragma unroll
                for (int m = 4; m < 32; m <<= 1) {
                    s0 += __shfl_xor_sync(0xFFFFFFFFu, s0, m);
                    s1 += __shfl_xor_sync(0xFFFFFFFFu, s1, m);
                    q0 += __shfl_xor_sync(0xFFFFFFFFu, q0, m);
                    q1 += __shfl_xor_sync(0xFFFFFFFFu, q1, m);
                }
                if ((lane >> 2) == 0) {
                    int c = nt * 8 + (lane & 3) * 2;
                    s_part[w * 80 + c]          = s0;
                    s_part[w * 80 + c + 1]      = s1;
                    s_part[w * 80 + 40 + c]     = q0;
                    s_part[w * 80 + 40 + c + 1] = q1;
                }
            }
            __syncthreads();
            if (tid < 80) {
                float a = 0.f;
#pragma unroll
                for (int ww = 0; ww < 8; ww++) a += s_part[ww * 80 + tid];
                int cta = (n * 24 + by) * 6 + bx;
                ppout[cta * 80 + tid] = a;
            }
        }
    }
}

#define C5_SMEM   (36 * 12 * ASTRIDE * 2 * 2)                         // 96768
#define GATE_A    (34 * 10 * ASTRIDE * 2 * 2)                         // 76160
#define GATE_SD   (256 * 57 * 4)                                      // 58368
#define GATE_SMEM (GATE_A > GATE_SD ? GATE_A : GATE_SD)

// ======================= driver =============================================
extern "C" void kernel_launch(void* const* d_in, const int* in_sizes, int n_in,
                              void* d_out, int out_size) {
    const float* x1  = (const float*)d_in[0];
    const float* x2  = (const float*)d_in[1];
    const float* Wf  = (const float*)d_in[2];
    const float* bf  = (const float*)d_in[3];
    const float* Wi  = (const float*)d_in[4];
    const float* bi  = (const float*)d_in[5];
    const float* Wc  = (const float*)d_in[6];
    const float* bc  = (const float*)d_in[7];
    const float* Wq  = (const float*)d_in[8];
    const float* bq  = (const float*)d_in[9];
    const float* W0  = (const float*)d_in[10];
    const float* g0  = (const float*)d_in[11];
    const float* be0 = (const float*)d_in[12];
    const float* W1  = (const float*)d_in[13];
    const float* g1  = (const float*)d_in[14];
    const float* be1 = (const float*)d_in[15];
    const float* W2  = (const float*)d_in[16];
    const float* b2w = (const float*)d_in[17];
    const float* Wh  = (const float*)d_in[18];
    const float* bh  = (const float*)d_in[19];
    float* out = (float*)d_out;

    float *hs, *r, *y0, *y1, *pp0, *pp1, *st0, *st1, *bg, *bho;
    uint2 *w0k16, *w1k16, *wgk16, *whk16;
    uint32_t *w0k8, *w1k8, *wgk8, *whk8;
    cudaGetSymbolAddress((void**)&hs,    g_hs);
    cudaGetSymbolAddress((void**)&r,     g_r);
    cudaGetSymbolAddress((void**)&y0,    g_y0);
    cudaGetSymbolAddress((void**)&y1,    g_y1);
    cudaGetSymbolAddress((void**)&pp0,   g_pp0);
    cudaGetSymbolAddress((void**)&pp1,   g_pp1);
    cudaGetSymbolAddress((void**)&st0,   g_st0);
    cudaGetSymbolAddress((void**)&st1,   g_st1);
    cudaGetSymbolAddress((void**)&bg,    g_bg);
    cudaGetSymbolAddress((void**)&bho,   g_bho);
    cudaGetSymbolAddress((void**)&w0k16, g_w0k16);
    cudaGetSymbolAddress((void**)&w0k8,  g_w0k8);
    cudaGetSymbolAddress((void**)&w1k16, g_w1k16);
    cudaGetSymbolAddress((void**)&w1k8,  g_w1k8);
    cudaGetSymbolAddress((void**)&wgk16, g_wgk16);
    cudaGetSymbolAddress((void**)&wgk8,  g_wgk8);
    cudaGetSymbolAddress((void**)&whk16, g_whk16);
    cudaGetSymbolAddress((void**)&whk8,  g_whk8);

    cudaFuncSetAttribute((const void*)conv_mma<3, 7, 32, false, 1, false>,
                         cudaFuncAttributeMaxDynamicSharedMemorySize, GATE_SMEM);
    cudaFuncSetAttribute((const void*)conv_mma<5, 5, 40, false, 0, true>,
                         cudaFuncAttributeMaxDynamicSharedMemorySize, C5_SMEM);
    cudaFuncSetAttribute((const void*)conv_mma<5, 5, 40, true, 0, true>,
                         cudaFuncAttributeMaxDynamicSharedMemorySize, C5_SMEM);
    cudaFuncSetAttribute((const void*)conv_mma<5, 2, 40, true, 2, false>,
                         cudaFuncAttributeMaxDynamicSharedMemorySize, C5_SMEM);

    // launch 0: init (zero state + build Wg/Who)
    init0<<<1024, 256>>>(Wf, bf, Wi, bi, Wc, bc, Wq, bq, Wh, bh, W2, b2w);
    // launch 1: pack all fragments
    prep_frags<<<(FRAG_TOTAL + 255) / 256, 256>>>(W0, W1);

    for (int t = 0; t < ND; t++) {
        for (int s = 0; s < 2; s++) {
            const float* x = (s == 0 ? x1 : x2) + (size_t)t * 32 * HW;
            float* oslice = out + (size_t)s * (NB * 3 * ND * HW) + (size_t)t * HW;

            // gate conv 3x3 (mma) + fused LSTM pointwise -> r = [c'|sig(q)]
            conv_mma<3, 7, 32, false, 1, false>
                <<<dim3(6, 24, NB), NTHR, GATE_SMEM>>>(
                    x, ND * 32 * HW, hs, 8 * HW, wgk16, wgk8, bg,
                    nullptr, nullptr, r, nullptr);

            // conv0 5x5 40->40 (mma, raw output, emits BN partials)
            conv_mma<5, 5, 40, false, 0, true>
                <<<dim3(6, 24, NB), NTHR, C5_SMEM>>>(
                    r, 40 * HW, nullptr, 0, w0k16, w0k8, nullptr,
                    nullptr, pp0, y0, nullptr);

            // reduce y0 partials -> scale/shift
            bn_reduce<<<1, 256>>>(pp0, g0, be0, st0);

            // conv1 5x5 40->40 (mma, BN+ReLU of y0 fused, emits BN partials)
            conv_mma<5, 5, 40, true, 0, true>
                <<<dim3(6, 24, NB), NTHR, C5_SMEM>>>(
                    y0, 40 * HW, nullptr, 0, w1k16, w1k8, nullptr,
                    st0, pp1, y1, nullptr);

            // reduce y1 partials -> scale/shift
            bn_reduce<<<1, 256>>>(pp1, g1, be1, st1);

            // fused h-state (3x3 embedded) + output head (5x5), mma
            conv_mma<5, 2, 40, true, 2, false>
                <<<dim3(6, 24, NB), NTHR, C5_SMEM>>>(
                    y1, 40 * HW, nullptr, 0, whk16, whk8, bho,
                    st1, nullptr, hs, oslice);
        }
    }
}

// round 12
// speedup vs baseline: 1.0772x; 1.0772x over previous
#include <cuda_runtime.h>
#include <cuda_bf16.h>
#include <cstdint>
#include <math.h>

#define HH 192
#define WWID 192
#define HW (192*192)
#define NB 4
#define ND 8
#define NCTA (6 * 24 * NB)      // conv grid CTAs = 576

// ======================= mma / ldmatrix helpers (sm_80+ PTX) ================
__device__ __forceinline__ void ldmx4(uint32_t addr, uint32_t* r) {
    asm volatile("ldmatrix.sync.aligned.m8n8.x4.shared.b16 {%0,%1,%2,%3}, [%4];"
        : "=r"(r[0]), "=r"(r[1]), "=r"(r[2]), "=r"(r[3]) : "r"(addr));
}
__device__ __forceinline__ void ldmx2(uint32_t addr, uint32_t* r) {
    asm volatile("ldmatrix.sync.aligned.m8n8.x2.shared.b16 {%0,%1}, [%2];"
        : "=r"(r[0]), "=r"(r[1]) : "r"(addr));
}
__device__ __forceinline__ void mma16816(float* d, const uint32_t* a, uint2 b) {
    asm volatile("mma.sync.aligned.m16n8k16.row.col.f32.bf16.bf16.f32 "
        "{%0,%1,%2,%3}, {%4,%5,%6,%7}, {%8,%9}, {%0,%1,%2,%3};"
        : "+f"(d[0]), "+f"(d[1]), "+f"(d[2]), "+f"(d[3])
        : "r"(a[0]), "r"(a[1]), "r"(a[2]), "r"(a[3]), "r"(b.x), "r"(b.y));
}
__device__ __forceinline__ void mma1688(float* d, const uint32_t* a, uint32_t b) {
    asm volatile("mma.sync.aligned.m16n8k8.row.col.f32.bf16.bf16.f32 "
        "{%0,%1,%2,%3}, {%4,%5}, {%6}, {%0,%1,%2,%3};"
        : "+f"(d[0]), "+f"(d[1]), "+f"(d[2]), "+f"(d[3])
        : "r"(a[0]), "r"(a[1]), "r"(b));
}
__device__ __forceinline__ uint32_t smem_u32(const void* p) {
    uint32_t a;
    asm("{ .reg .u64 t; cvta.to.shared.u64 t, %1; cvt.u32.u64 %0, t; }" : "=r"(a) : "l"(p));
    return a;
}
__device__ __forceinline__ unsigned short bfbits(float v) {
    return __bfloat16_as_ushort(__float2bfloat16(v));
}
__device__ __forceinline__ float fsig(float x) {
    return __fdividef(1.f, 1.f + __expf(-x));
}
__device__ __forceinline__ float ftanh(float x) {
    return 1.f - __fdividef(2.f, __expf(2.f * x) + 1.f);
}

// ======================= scratch ============================================
__device__ float g_hs[NB * 8 * HW];
__device__ float g_r [NB * 40 * HW];     // [c_state(8) | q(32)]
__device__ float g_y0[NB * 40 * HW];
__device__ float g_y1[NB * 40 * HW];
__device__ float g_pp0[80 * NCTA];       // transposed partials: [stat][cta]
__device__ float g_pp1[80 * NCTA];
__device__ float g_st0[80];              // scale|shift for y0
__device__ float g_st1[80];              // scale|shift for y1
__device__ float g_Wg[56 * 40 * 9];
__device__ float g_bg[56];
__device__ float g_Who[16 * 40 * 25];    // fused h(3x3 embedded) + out(5x5)
__device__ float g_bho[16];
// packed mma weight fragments (k16 pairs + k8 tail), bf16 hi/lo terms
__device__ uint2    g_w0k16[25 * 2 * 5 * 2 * 32];
__device__ uint32_t g_w0k8 [25 * 5 * 2 * 32];
__device__ uint2    g_w1k16[25 * 2 * 5 * 2 * 32];
__device__ uint32_t g_w1k8 [25 * 5 * 2 * 32];
__device__ uint2    g_wgk16[9 * 2 * 7 * 2 * 32];
__device__ uint32_t g_wgk8 [9 * 7 * 2 * 32];
__device__ uint2    g_whk16[25 * 2 * 2 * 2 * 32];
__device__ uint32_t g_whk8 [25 * 2 * 2 * 32];

// ======================= setup kernel 1: zero state + build Wg/Who ==========
__global__ void init0(const float* __restrict__ Wf, const float* __restrict__ bf,
                      const float* __restrict__ Wi, const float* __restrict__ bi,
                      const float* __restrict__ Wc, const float* __restrict__ bc,
                      const float* __restrict__ Wq, const float* __restrict__ bq,
                      const float* __restrict__ Wh, const float* __restrict__ bh,
                      const float* __restrict__ W2, const float* __restrict__ b2w) {
    int stride = gridDim.x * blockDim.x;
    int i0 = blockIdx.x * blockDim.x + threadIdx.x;
    for (int i = i0; i < NB * 8 * HW; i += stride) g_hs[i] = 0.f;
    for (int i = i0; i < NB * 40 * HW; i += stride) g_r[i] = 0.f;

    const int WSZ = 40 * 9;
    int i = i0;
    if (i < 56 * WSZ) {
        int cout = i / WSZ, rest = i - cout * WSZ;
        float v;
        if (cout < 8)       v = Wf[cout * WSZ + rest];
        else if (cout < 16) v = Wi[(cout - 8) * WSZ + rest];
        else if (cout < 24) v = Wc[(cout - 16) * WSZ + rest];
        else                v = Wq[(cout - 24) * WSZ + rest];
        g_Wg[i] = v;
    }
    if (i < 56) {
        float v;
        if (i < 8)       v = bf[i];
        else if (i < 16) v = bi[i - 8];
        else if (i < 24) v = bc[i - 16];
        else             v = bq[i - 24];
        g_bg[i] = v;
    }
    if (i < 16 * 40 * 25) {
        int tap = i % 25; int rest = i / 25;
        int k = rest % 40; int nn = rest / 40;
        int ky = tap / 5, kx = tap % 5;
        float v = 0.f;
        if (nn < 8) {
            if (ky >= 1 && ky <= 3 && kx >= 1 && kx <= 3)
                v = Wh[(nn * 40 + k) * 9 + (ky - 1) * 3 + (kx - 1)];
        } else if (nn < 11) {
            v = W2[((nn - 8) * 40 + k) * 25 + tap];
        }
        g_Who[i] = v;
    }
    if (i < 16) g_bho[i] = (i < 8) ? bh[i] : (i < 11 ? b2w[i - 8] : 0.f);
}

// ======================= setup kernel 2: pack all mma fragments =============
__device__ void pk16_one(const float* __restrict__ W, uint2* __restrict__ dst,
                         int TAPS, int NT, int i) {
    int lane = i & 31; int r = i >> 5;
    int term = r & 1; r >>= 1;
    int nt = r % NT;  r /= NT;
    int kt = r & 1;   int tap = r >> 1;
    int nn = nt * 8 + (lane >> 2);
    int k0 = kt * 16 + (lane & 3) * 2;
    unsigned short h[4];
#pragma unroll
    for (int j = 0; j < 4; j++) {
        int kk = k0 + (j & 1) + (j >> 1) * 8;
        float v = W[(nn * 40 + kk) * TAPS + tap];
        unsigned short hb = bfbits(v);
        if (term == 0) h[j] = hb;
        else h[j] = bfbits(v - __bfloat162float(__ushort_as_bfloat16(hb)));
    }
    dst[i] = make_uint2((uint32_t)h[0] | ((uint32_t)h[1] << 16),
                        (uint32_t)h[2] | ((uint32_t)h[3] << 16));
}
__device__ void pk8_one(const float* __restrict__ W, uint32_t* __restrict__ dst,
                        int TAPS, int NT, int i) {
    int lane = i & 31; int r = i >> 5;
    int term = r & 1; r >>= 1;
    int nt = r % NT;  int tap = r / NT;
    int nn = nt * 8 + (lane >> 2);
    int k0 = 32 + (lane & 3) * 2;
    unsigned short h[2];
#pragma unroll
    for (int j = 0; j < 2; j++) {
        float v = W[(nn * 40 + k0 + j) * TAPS + tap];
        unsigned short hb = bfbits(v);
        if (term == 0) h[j] = hb;
        else h[j] = bfbits(v - __bfloat162float(__ushort_as_bfloat16(hb)));
    }
    dst[i] = (uint32_t)h[0] | ((uint32_t)h[1] << 16);
}

// segment offsets (exact fragment counts)
#define FRAG_TOTAL 69696
__global__ void prep_frags(const float* __restrict__ W0, const float* __restrict__ W1) {
    int i = blockIdx.x * blockDim.x + threadIdx.x;
    if      (i < 16000) pk16_one(W0, g_w0k16, 25, 5, i);
    else if (i < 24000) pk8_one (W0, g_w0k8,  25, 5, i - 16000);
    else if (i < 40000) pk16_one(W1, g_w1k16, 25, 5, i - 24000);
    else if (i < 48000) pk8_one (W1, g_w1k8,  25, 5, i - 40000);
    else if (i < 56064) pk16_one(g_Wg, g_wgk16, 9, 7, i - 48000);
    else if (i < 60096) pk8_one (g_Wg, g_wgk8,  9, 7, i - 56064);
    else if (i < 66496) pk16_one(g_Who, g_whk16, 25, 2, i - 60096);
    else if (i < 69696) pk8_one (g_Who, g_whk8,  25, 2, i - 66496);
}

// ======================= BN reduce: [80][576] -> scale/shift[80] ============
// grid 40 blocks; block c reduces stat rows c (sum) and 40+c (sumsq), coalesced.
__global__ void bn_reduce(const float* __restrict__ pp, const float* __restrict__ gamma,
                          const float* __restrict__ beta, float* __restrict__ st) {
    int c = blockIdx.x;
    int tid = threadIdx.x;
    const float* ps = pp + (size_t)c * NCTA;
    const float* pq = pp + (size_t)(40 + c) * NCTA;
    float s = 0.f, q = 0.f;
    for (int i = tid; i < NCTA; i += 256) { s += ps[i]; q += pq[i]; }
    __shared__ float rs[256], rq[256];
    rs[tid] = s; rq[tid] = q;
    __syncthreads();
    for (int off = 128; off > 0; off >>= 1) {
        if (tid < off) { rs[tid] += rs[tid + off]; rq[tid] += rq[tid + off]; }
        __syncthreads();
    }
    if (tid == 0) {
        const float Ninv = 1.f / (float)(NB * HW);
        float mean = rs[0] * Ninv;
        float var  = rq[0] * Ninv - mean * mean;
        float sc   = gamma[c] * rsqrtf(var + 1e-5f);
        st[c] = sc;
        st[40 + c] = beta[c] - mean * sc;
    }
}

// ======================= generic mma conv (CIN=40, bf16 3-term, K=40) =======
// CTA: 256 thr / 8 warps; out tile 32x8 pixels; COUT = NT*8.
// MODE 0: plain 40-ch output (STATS: emit transposed per-CTA BN partials).
// MODE 1: LSTM epilogue -> out = r buffer (old c in ch0-7), bias = gate biases.
// MODE 2: HOUT epilogue -> out = h-state (8ch) + out2 = p_depth (3ch), biased.
#define ASTRIDE 56
#define NTHR 256

template<int KK, int NT, int CA, bool PREOP, int MODE, bool STATS>
__global__ void __launch_bounds__(NTHR, 2)
conv_mma(const float* __restrict__ inA, int strideA,
         const float* __restrict__ inB, int strideB,
         const uint2* __restrict__ wk16,
         const uint32_t* __restrict__ wk8,
         const float* __restrict__ bias,
         const float* __restrict__ stats_in,
         float* __restrict__ ppout,
         float* __restrict__ out,
         float* __restrict__ out2)
{
    constexpr int TW = 32 + KK - 1;
    constexpr int TH = 8 + KK - 1;
    constexpr int NPIX = TW * TH;
    constexpr int PADK = KK / 2;
    constexpr int APL = NPIX * ASTRIDE * 2;     // bytes per bf16 plane

    extern __shared__ char dsm[];
    __shared__ float s_sc[40], s_sh[40];
    __shared__ float s_bias[56];
    __shared__ float s_part[STATS ? 8 * 80 : 1];
    __nv_bfloat16* Ah = (__nv_bfloat16*)dsm;
    __nv_bfloat16* Al = (__nv_bfloat16*)(dsm + APL);

    const int tid = threadIdx.x;
    const int w = tid >> 5, lane = tid & 31;
    const int bx = blockIdx.x, by = blockIdx.y, n = blockIdx.z;

    if constexpr (MODE == 1) {
        if (tid < 56) s_bias[tid] = bias[tid];
    }
    if constexpr (MODE == 2) {
        if (tid < 16) s_bias[tid] = bias[tid];
    }
    if constexpr (PREOP) {
        if (tid < 40) { s_sc[tid] = stats_in[tid]; s_sh[tid] = stats_in[40 + tid]; }
        __syncthreads();
    }

    // ---- stage input tile (fused concat), split bf16 hi/lo -----------------
    const int x0 = bx * 32 - PADK, y0 = by * 8 - PADK;
    for (int i = tid; i < 40 * NPIX; i += NTHR) {
        int cin = i / NPIX, pix = i - cin * NPIX;
        int pr = pix / TW, pc = pix - pr * TW;
        int yy = y0 + pr, xx = x0 + pc;
        float v = 0.f;
        if (yy >= 0 && yy < HH && xx >= 0 && xx < WWID) {
            const float* src = (cin < CA)
                ? (inA + (size_t)n * strideA + (size_t)cin * HW)
                : (inB + (size_t)n * strideB + (size_t)(cin - CA) * HW);
            v = src[yy * WWID + xx];
            if constexpr (PREOP) v = fmaxf(fmaf(s_sc[cin], v, s_sh[cin]), 0.f);
        }
        __nv_bfloat16 h = __float2bfloat16(v);
        __nv_bfloat16 l = __float2bfloat16(v - __bfloat162float(h));
        Ah[pix * ASTRIDE + cin] = h;
        Al[pix * ASTRIDE + cin] = l;
    }
    __syncthreads();

    const uint32_t ah_base = smem_u32(Ah);
    const uint32_t al_base = ah_base + APL;
    const int lrow = lane & 15;
    const int lcolB = (lane >> 4) * 16;

    float d[2][NT][4];
#pragma unroll
    for (int mt = 0; mt < 2; mt++)
#pragma unroll
        for (int nt = 0; nt < NT; nt++)
#pragma unroll
            for (int j = 0; j < 4; j++) d[mt][nt][j] = 0.f;

    const uint2* wt16 = wk16;
    const uint32_t* wt8 = wk8;
    for (int ky = 0; ky < KK; ky++) {
        const uint32_t rowk = (uint32_t)((w + ky) * TW + lrow) * (ASTRIDE * 2);
#pragma unroll
        for (int kx = 0; kx < KK; kx++) {
            uint32_t a_h[2][2][4], a_l[2][2][4];   // [kt][mt]
            uint32_t a_h8[2][2], a_l8[2][2];       // [mt]
#pragma unroll
            for (int mt = 0; mt < 2; mt++) {
                uint32_t rb = rowk + (uint32_t)(mt * 16) * (ASTRIDE * 2)
                            + (uint32_t)kx * (ASTRIDE * 2);
                ldmx4(ah_base + rb + lcolB, a_h[0][mt]);
                ldmx4(ah_base + rb + 32 + lcolB, a_h[1][mt]);
                ldmx2(ah_base + rb + 64, a_h8[mt]);
                ldmx4(al_base + rb + lcolB, a_l[0][mt]);
                ldmx4(al_base + rb + 32 + lcolB, a_l[1][mt]);
                ldmx2(al_base + rb + 64, a_l8[mt]);
            }
#pragma unroll
            for (int kt = 0; kt < 2; kt++) {
#pragma unroll
                for (int nt = 0; nt < NT; nt++) {
                    uint2 bh = wt16[((kt * NT + nt) * 2 + 0) * 32 + lane];
                    uint2 bl = wt16[((kt * NT + nt) * 2 + 1) * 32 + lane];
#pragma unroll
                    for (int mt = 0; mt < 2; mt++) {
                        mma16816(d[mt][nt], a_h[kt][mt], bh);
                        mma16816(d[mt][nt], a_l[kt][mt], bh);
                        mma16816(d[mt][nt], a_h[kt][mt], bl);
                    }
                }
            }
#pragma unroll
            for (int nt = 0; nt < NT; nt++) {
                uint32_t bh8 = wt8[(nt * 2 + 0) * 32 + lane];
                uint32_t bl8 = wt8[(nt * 2 + 1) * 32 + lane];
#pragma unroll
                for (int mt = 0; mt < 2; mt++) {
                    mma1688(d[mt][nt], a_h8[mt], bh8);
                    mma1688(d[mt][nt], a_l8[mt], bh8);
                    mma1688(d[mt][nt], a_h8[mt], bl8);
                }
            }
            wt16 += 2 * NT * 2 * 32;
            wt8  += NT * 2 * 32;
        }
    }

    if constexpr (MODE == 1) {
        // ---- stash D (256 pix x 56 ch) to smem, then LSTM pointwise --------
        __syncthreads();                      // A planes dead; reuse dsm
        float* sd = (float*)dsm;              // [256][57]
#pragma unroll
        for (int mt = 0; mt < 2; mt++) {
            int px = mt * 16 + (lane >> 2);
#pragma unroll
            for (int nt = 0; nt < NT; nt++) {
                int c = nt * 8 + (lane & 3) * 2;
                sd[(w * 32 + px) * 57 + c]           = d[mt][nt][0];
                sd[(w * 32 + px) * 57 + c + 1]       = d[mt][nt][1];
                sd[(w * 32 + px + 8) * 57 + c]       = d[mt][nt][2];
                sd[(w * 32 + px + 8) * 57 + c + 1]   = d[mt][nt][3];
            }
        }
        __syncthreads();
        const float* sp = sd + tid * 57;
        int gy = by * 8 + (tid >> 5);
        int gx = bx * 32 + (tid & 31);
        float* rb = out + (size_t)n * 40 * HW + gy * WWID + gx;
#pragma unroll
        for (int c = 0; c < 8; c++) {
            float f  = fsig(sp[c] + s_bias[c]);
            float ii = fsig(sp[8 + c] + s_bias[8 + c]);
            float gg = ftanh(sp[16 + c] + s_bias[16 + c]);
            float co = rb[(size_t)c * HW];
            rb[(size_t)c * HW] = f * co + ii * gg;
        }
#pragma unroll
        for (int j = 0; j < 32; j++) {
            rb[(size_t)(8 + j) * HW] = fsig(sp[24 + j] + s_bias[24 + j]);
        }
    } else if constexpr (MODE == 2) {
        // ---- dual epilogue: nt0 -> h-state (8ch), nt1 -> p_depth (3ch) -----
        const int gy = by * 8 + w;
#pragma unroll
        for (int mt = 0; mt < 2; mt++) {
            int gx = bx * 32 + mt * 16 + (lane >> 2);
            {
                int c = (lane & 3) * 2;
                float* hb = out + ((size_t)n * 8 + c) * HW + gy * WWID + gx;
                hb[0]      = d[mt][0][0] + s_bias[c];
                hb[HW]     = d[mt][0][1] + s_bias[c + 1];
                hb[8]      = d[mt][0][2] + s_bias[c];
                hb[HW + 8] = d[mt][0][3] + s_bias[c + 1];
            }
            {
                int oc = (lane & 3) * 2;
                if (oc < 3) {
                    float* ob = out2 + (size_t)n * 3 * ND * HW
                              + (size_t)oc * ND * HW + gy * WWID + gx;
                    ob[0] = d[mt][1][0] + s_bias[8 + oc];
                    ob[8] = d[mt][1][2] + s_bias[8 + oc];
                    if (oc + 1 < 3) {
                        ob[(size_t)ND * HW]     = d[mt][1][1] + s_bias[9 + oc];
                        ob[(size_t)ND * HW + 8] = d[mt][1][3] + s_bias[9 + oc];
                    }
                }
            }
        }
    } else {
        const int gy = by * 8 + w;
#pragma unroll
        for (int mt = 0; mt < 2; mt++) {
            int gx = bx * 32 + mt * 16 + (lane >> 2);
#pragma unroll
            for (int nt = 0; nt < NT; nt++) {
                int c = nt * 8 + (lane & 3) * 2;
                float* ob = out + ((size_t)n * 40 + c) * HW + gy * WWID + gx;
                ob[0]      = d[mt][nt][0];
                ob[HW]     = d[mt][nt][1];
                ob[8]      = d[mt][nt][2];
                ob[HW + 8] = d[mt][nt][3];
            }
        }
        if constexpr (STATS) {
            // per-CTA BN partials: sum/sumsq per channel over 256 pixels
#pragma unroll
            for (int nt = 0; nt < NT; nt++) {
                float s0 = d[0][nt][0] + d[0][nt][2] + d[1][nt][0] + d[1][nt][2];
                float s1 = d[0][nt][1] + d[0][nt][3] + d[1][nt][1] + d[1][nt][3];
                float q0 = d[0][nt][0]*d[0][nt][0] + d[0][nt][2]*d[0][nt][2]
                         + d[1][nt][0]*d[1][nt][0] + d[1][nt][2]*d[1][nt][2];
                float q1 = d[0][nt][1]*d[0][nt][1] + d[0][nt][3]*d[0][nt][3]
                         + d[1][nt][1]*d[1][nt][1] + d[1][nt][3]*d[1][nt][3];
#pragma unroll
                for (int m = 4; m < 32; m <<= 1) {
                    s0 += __shfl_xor_sync(0xFFFFFFFFu, s0, m);
                    s1 += __shfl_xor_sync(0xFFFFFFFFu, s1, m);
                    q0 += __shfl_xor_sync(0xFFFFFFFFu, q0, m);
                    q1 += __shfl_xor_sync(0xFFFFFFFFu, q1, m);
                }
                if ((lane >> 2) == 0) {
                    int c = nt * 8 + (lane & 3) * 2;
                    s_part[w * 80 + c]          = s0;
                    s_part[w * 80 + c + 1]      = s1;
                    s_part[w * 80 + 40 + c]     = q0;
                    s_part[w * 80 + 40 + c + 1] = q1;
                }
            }
            __syncthreads();
            if (tid < 80) {
                float a = 0.f;
#pragma unroll
                for (int ww = 0; ww < 8; ww++) a += s_part[ww * 80 + tid];
                int cta = (n * 24 + by) * 6 + bx;
                ppout[(size_t)tid * NCTA + cta] = a;   // transposed
            }
        }
    }
}

#define C5_SMEM   (36 * 12 * ASTRIDE * 2 * 2)                         // 96768
#define GATE_A    (34 * 10 * ASTRIDE * 2 * 2)                         // 76160
#define GATE_SD   (256 * 57 * 4)                                      // 58368
#define GATE_SMEM (GATE_A > GATE_SD ? GATE_A : GATE_SD)

// ======================= driver =============================================
extern "C" void kernel_launch(void* const* d_in, const int* in_sizes, int n_in,
                              void* d_out, int out_size) {
    const float* x1  = (const float*)d_in[0];
    const float* x2  = (const float*)d_in[1];
    const float* Wf  = (const float*)d_in[2];
    const float* bf  = (const float*)d_in[3];
    const float* Wi  = (const float*)d_in[4];
    const float* bi  = (const float*)d_in[5];
    const float* Wc  = (const float*)d_in[6];
    const float* bc  = (const float*)d_in[7];
    const float* Wq  = (const float*)d_in[8];
    const float* bq  = (const float*)d_in[9];
    const float* W0  = (const float*)d_in[10];
    const float* g0  = (const float*)d_in[11];
    const float* be0 = (const float*)d_in[12];
    const float* W1  = (const float*)d_in[13];
    const float* g1  = (const float*)d_in[14];
    const float* be1 = (const float*)d_in[15];
    const float* W2  = (const float*)d_in[16];
    const float* b2w = (const float*)d_in[17];
    const float* Wh  = (const float*)d_in[18];
    const float* bh  = (const float*)d_in[19];
    float* out = (float*)d_out;

    float *hs, *r, *y0, *y1, *pp0, *pp1, *st0, *st1, *bg, *bho;
    uint2 *w0k16, *w1k16, *wgk16, *whk16;
    uint32_t *w0k8, *w1k8, *wgk8, *whk8;
    cudaGetSymbolAddress((void**)&hs,    g_hs);
    cudaGetSymbolAddress((void**)&r,     g_r);
    cudaGetSymbolAddress((void**)&y0,    g_y0);
    cudaGetSymbolAddress((void**)&y1,    g_y1);
    cudaGetSymbolAddress((void**)&pp0,   g_pp0);
    cudaGetSymbolAddress((void**)&pp1,   g_pp1);
    cudaGetSymbolAddress((void**)&st0,   g_st0);
    cudaGetSymbolAddress((void**)&st1,   g_st1);
    cudaGetSymbolAddress((void**)&bg,    g_bg);
    cudaGetSymbolAddress((void**)&bho,   g_bho);
    cudaGetSymbolAddress((void**)&w0k16, g_w0k16);
    cudaGetSymbolAddress((void**)&w0k8,  g_w0k8);
    cudaGetSymbolAddress((void**)&w1k16, g_w1k16);
    cudaGetSymbolAddress((void**)&w1k8,  g_w1k8);
    cudaGetSymbolAddress((void**)&wgk16, g_wgk16);
    cudaGetSymbolAddress((void**)&wgk8,  g_wgk8);
    cudaGetSymbolAddress((void**)&whk16, g_whk16);
    cudaGetSymbolAddress((void**)&whk8,  g_whk8);

    cudaFuncSetAttribute((const void*)conv_mma<3, 7, 32, false, 1, false>,
                         cudaFuncAttributeMaxDynamicSharedMemorySize, GATE_SMEM);
    cudaFuncSetAttribute((const void*)conv_mma<5, 5, 40, false, 0, true>,
                         cudaFuncAttributeMaxDynamicSharedMemorySize, C5_SMEM);
    cudaFuncSetAttribute((const void*)conv_mma<5, 5, 40, true, 0, true>,
                         cudaFuncAttributeMaxDynamicSharedMemorySize, C5_SMEM);
    cudaFuncSetAttribute((const void*)conv_mma<5, 2, 40, true, 2, false>,
                         cudaFuncAttributeMaxDynamicSharedMemorySize, C5_SMEM);

    // launch 0: init (zero state + build Wg/Who)
    init0<<<1024, 256>>>(Wf, bf, Wi, bi, Wc, bc, Wq, bq, Wh, bh, W2, b2w);
    // launch 1: pack all fragments
    prep_frags<<<(FRAG_TOTAL + 255) / 256, 256>>>(W0, W1);

    for (int t = 0; t < ND; t++) {
        for (int s = 0; s < 2; s++) {
            const float* x = (s == 0 ? x1 : x2) + (size_t)t * 32 * HW;
            float* oslice = out + (size_t)s * (NB * 3 * ND * HW) + (size_t)t * HW;

            // gate conv 3x3 (mma) + fused LSTM pointwise -> r = [c'|sig(q)]
            conv_mma<3, 7, 32, false, 1, false>
                <<<dim3(6, 24, NB), NTHR, GATE_SMEM>>>(
                    x, ND * 32 * HW, hs, 8 * HW, wgk16, wgk8, bg,
                    nullptr, nullptr, r, nullptr);

            // conv0 5x5 40->40 (mma, raw output, emits BN partials)
            conv_mma<5, 5, 40, false, 0, true>
                <<<dim3(6, 24, NB), NTHR, C5_SMEM>>>(
                    r, 40 * HW, nullptr, 0, w0k16, w0k8, nullptr,
                    nullptr, pp0, y0, nullptr);

            // reduce y0 partials -> scale/shift (40 blocks, coalesced)
            bn_reduce<<<40, 256>>>(pp0, g0, be0, st0);

            // conv1 5x5 40->40 (mma, BN+ReLU of y0 fused, emits BN partials)
            conv_mma<5, 5, 40, true, 0, true>
                <<<dim3(6, 24, NB), NTHR, C5_SMEM>>>(
                    y0, 40 * HW, nullptr, 0, w1k16, w1k8, nullptr,
                    st0, pp1, y1, nullptr);

            // reduce y1 partials -> scale/shift
            bn_reduce<<<40, 256>>>(pp1, g1, be1, st1);

            // fused h-state (3x3 embedded) + output head (5x5), mma
            conv_mma<5, 2, 40, true, 2, false>
                <<<dim3(6, 24, NB), NTHR, C5_SMEM>>>(
                    y1, 40 * HW, nullptr, 0, whk16, whk8, bho,
                    st1, nullptr, hs, oslice);
        }
    }
}